// round 11
// baseline (speedup 1.0000x reference)
#include <cuda_runtime.h>
#include <math.h>

#define NSPEC  256
#define NSPEC3 5456
#define NPACK  2856   // sum over l of (2l+1)*(l+1)  — only nloc >= l kept

// scratch (static device globals — allowed)
__device__ float2 g_fhat [16*16*NSPEC];     // [b][f][s]
__device__ float2 g_psi  [16*64*NSPEC];     // [i][o][s]
__device__ float2 g_Fz   [1024*NPACK];      // [b*64+o][packed e]  (23.4 MB)
__device__ float  g_wig3p[32*NPACK];        // packed wig_so3
__device__ int    g_lut  [NPACK];           // packed (sm_ << 16) | sn for k_fz

__constant__ int c_offs[16] = {0,1,10,35,84,165,286,455,680,969,1330,1771,2300,2925,3654,4495};
__constant__ int c_offP[16] = {0,1,7,22,50,95,161,252,372,525,715,946,1222,1547,1925,2360};
// c_step[l] = (2l+3)(l+1): idx_{l+1} = idx_l + c_step[l] + m
__constant__ int c_step[15] = {3,10,21,36,55,78,105,136,171,210,253,300,351,406,465};

// ---------------- Kernel 1: fhat[b,f,s] (Hermitian fold over m + radix-2 fold over alpha) ----------------
__global__ void k_fhat(const float* __restrict__ x, const float* __restrict__ wig) {
    __shared__ float buf[8512];
    float*  sx   = buf;                       // [j*65 + a], a<64
    float2* xf   = (float2*)buf;              // [j*16 + m], m<16 (aliases sx after it is dead)
    float*  su   = buf + 4160;                // [j*33 + a], a<32: x[a]+x[a+32]
    float*  sv   = buf + 6272;                // [j*33 + a], a<32: x[a]-x[a+32]
    float2* cs64 = (float2*)(buf + 8384);     // e^{-2pi i t/64}
    int b = blockIdx.x, f = blockIdx.y, tid = threadIdx.x;
    if (tid < 64) { float sv_, cv; sincospif((float)tid/32.0f, &sv_, &cv); cs64[tid] = make_float2(cv, -sv_); }
    const float* xp = x + (size_t)(b*16+f)*4096;
    for (int p = tid; p < 4096; p += 256) sx[(p>>6)*65 + (p&63)] = xp[p];
    __syncthreads();
    for (int p = tid; p < 2048; p += 256) {           // u/v fold: 64 j x 32 a
        int j = p >> 5, a = p & 31;
        float lo = sx[j*65 + a], hi = sx[j*65 + a + 32];
        su[j*33 + a] = lo + hi;
        sv[j*33 + a] = lo - hi;
    }
    __syncthreads();
    for (int p = tid; p < 1024; p += 256) {           // 16 m-values (0..15) x 64 betas, 32 iters
        int m = p >> 6, j = p & 63;
        const float* row = (m & 1) ? &sv[j*33] : &su[j*33];
        float ar=0.f, ai=0.f;
        int t = 0;
        #pragma unroll 8
        for (int a = 0; a < 32; a++) {
            float2 e = cs64[t];                        // broadcast
            float v = row[a];
            ar += v*e.x;
            ai += v*e.y;
            t = (t + m) & 63;
        }
        xf[j*16+m] = make_float2(ar, ai);              // overwrites dead sx region
    }
    __syncthreads();
    int s = tid;
    int l = (int)sqrtf((float)s);
    while ((l+1)*(l+1) <= s) ++l;
    while (l*l > s) --l;
    int m = s - l*l - l;
    int am = m < 0 ? -m : m;
    float sgn = m < 0 ? -1.f : 1.f;                    // xf[-m] = conj(xf[m])
    float ar=0.f, ai=0.f;
    #pragma unroll 8
    for (int j = 0; j < 64; j++) {
        float w = wig[j*NSPEC + s];
        float2 v = xf[j*16+am];
        ar += w*v.x; ai += w*v.y;
    }
    g_fhat[(b*16+f)*NSPEC + s] = make_float2(ar, sgn*ai);
}

// ---------------- Kernel 2 (merged): blocks 0..255 = psi, blocks 256..287 = pack wig_so3 + LUT ----------------
__global__ void k_prep(const float* __restrict__ kern, const float* __restrict__ fkr,
                       const float* __restrict__ fki, float scaling,
                       const float* __restrict__ wig3) {
    int tid = threadIdx.x;
    if (blockIdx.x < 256) {
        __shared__ float2 fk[32];
        int s = blockIdx.x;
        if (tid < 32) fk[tid] = make_float2(fkr[s*32+tid]*scaling, fki[s*32+tid]*scaling);
        __syncthreads();
        for (int p = tid; p < 1024; p += 256) {        // p = i*64+o
            const float* kp = kern + p*32;
            float ar=0.f, ai=0.f;
            #pragma unroll
            for (int g = 0; g < 32; g++) { float kv = kp[g]; ar += kv*fk[g].x; ai += kv*fk[g].y; }
            g_psi[p*NSPEC + s] = make_float2(ar, ai);
        }
    } else {
        int k = blockIdx.x - 256;
        for (int p = tid; p < NPACK; p += 256) {
            int l = 15;
            while (c_offP[l] > p) --l;
            int r = p - c_offP[l];
            int mloc = r / (l+1);
            int nq   = r - mloc*(l+1);
            g_wig3p[k*NPACK + p] = wig3[k*NSPEC3 + c_offs[l] + mloc*(2*l+1) + (nq + l)];
            if (k == 0) {
                int sm_ = l*l + mloc;
                int sn  = l*l + nq + l;
                g_lut[p] = (sm_ << 16) | sn;
            }
        }
    }
}

// ---------------- Kernel 3: packed Fz (only n >= 0), split even/odd-i accumulators for ILP ----------------
__global__ void k_fz() {
    extern __shared__ float2 sm3[];
    float2* fh = sm3;          // [i*256+s]
    float2* ps = sm3 + 4096;   // [i*256+s]
    int bo = blockIdx.x, b = bo >> 6, o = bo & 63, tid = threadIdx.x;
    for (int p = tid; p < 4096; p += 512) {
        int i = p >> 8, s = p & 255;
        fh[p] = g_fhat[(b*16+i)*NSPEC + s];            // coalesced
        ps[p] = g_psi [(i*64+o)*NSPEC + s];            // coalesced
    }
    __syncthreads();
    for (int e = tid; e < NPACK; e += 512) {
        int lu = __ldg(&g_lut[e]);
        int sm_ = lu >> 16, sn = lu & 0xffff;
        float ar0=0.f, ai0=0.f, ar1=0.f, ai1=0.f;      // two chains, halved latency depth
        #pragma unroll
        for (int i = 0; i < 16; i += 2) {
            float2 a0 = fh[i*256 + sm_];
            float2 c0 = ps[i*256 + sn];
            float2 a1 = fh[(i+1)*256 + sm_];
            float2 c1 = ps[(i+1)*256 + sn];
            ar0 += a0.x*c0.x + a0.y*c0.y;              // fhat * conj(psi)
            ai0 += a0.y*c0.x - a0.x*c0.y;
            ar1 += a1.x*c1.x + a1.y*c1.y;
            ai1 += a1.y*c1.x - a1.x*c1.y;
        }
        g_Fz[(size_t)bo*NPACK + e] = make_float2(ar0 + ar1, ai0 + ai1);
    }
}

// ---------------- Kernel 4 (fused, Hermitian + radix-4 both axes, dual-k) ----------------
// grid (1024 bo, 4 kq); each block handles 8 beta_out values, 2 at a time.
// smem float2 units: Fz 2856 | spc 1024 (2x512) | Vv 1024 (2x512) | cs16 496
// total = (2856+1024+1024+496)*8 = 43200 B -> 5 CTAs/SM
__global__ void k_main(const float* __restrict__ bias, float* __restrict__ out) {
    extern __shared__ float smraw[];
    float2* Fz   = (float2*)smraw;     // 2856
    float2* spc  = Fz  + 2856;         // 1024: [kp*512 + mi*16 + nq]
    float2* Vv   = spc + 1024;         // 1024: [kp*512 + a*16 + nq]
    float2* cs16 = Vv  + 1024;         // 496:  cs16[q*16+r] = e^{+2pi i (q-15) r/32}, r<16
    int tid = threadIdx.x;
    int bo = blockIdx.x, o = bo & 63;
    int kq = blockIdx.y;

    for (int p = tid; p < 496; p += 256) {
        int q = p >> 4, r = p & 15;
        int t = ((q-15)*r) & 31;
        float sv, cv; sincospif((float)t / 16.0f, &sv, &cv);
        cs16[p] = make_float2(cv, sv);
    }
    for (int p = tid; p < NPACK; p += 256) Fz[p] = g_Fz[(size_t)bo*NPACK + p];
    float bv = bias[o];

    int kp = tid >> 7, t2 = tid & 127;

    for (int kk4 = 0; kk4 < 4; kk4++) {
        int k = kq*8 + kk4*2 + kp;
        __syncthreads();                               // prior stage2 done before spc/Vv rewrite

        // spec[m,n] for n>=0 (half-block per k-plane), incremental packed index
        const float* wkg = g_wig3p + k*NPACK;
        for (int p = t2; p < 496; p += 128) {
            int mi = p >> 4, nq = p & 15;
            int m = mi - 15;
            int am = m < 0 ? -m : m;
            int lmin = am > nq ? am : nq;
            float ar = 0.f, ai = 0.f;
            int idx = c_offP[lmin] + (m+lmin)*(lmin+1) + nq;
            for (int l = lmin; l < 16; l++) {
                float d = __ldg(&wkg[idx]);
                float2 fz = Fz[idx];
                ar += fz.x*d;
                ai += fz.y*d;
                if (l < 15) idx += c_step[l] + m;
            }
            spc[kp*512 + p] = make_float2(ar, ai);
        }
        __syncthreads();

        // stage 1 (radix-4 over m): 31 cmacs -> V[a0], V[a0+8], V[a0+16], V[a0+24]
        {
            int a0 = t2 >> 4, n = t2 & 15;             // a0 in 0..7
            float s0r=0,s0i=0,s1r=0,s1i=0,s2r=0,s2i=0,s3r=0,s3i=0;
            #pragma unroll
            for (int mi = 0; mi < 31; mi++) {
                float2 sp = spc[kp*512 + mi*16 + n];
                float2 e  = cs16[mi*16 + a0];          // e^{+2pi i (mi-15) a0/32}
                float tr = sp.x*e.x - sp.y*e.y;
                float ti = sp.x*e.y + sp.y*e.x;
                int r = (mi + 1) & 3;                  // (mi-15) mod 4
                if      (r == 0) { s0r += tr; s0i += ti; }
                else if (r == 1) { s1r += tr; s1i += ti; }
                else if (r == 2) { s2r += tr; s2i += ti; }
                else             { s3r += tr; s3i += ti; }
            }
            float2* V = Vv + kp*512;
            V[(a0     )*16 + n] = make_float2(s0r + s1r + s2r + s3r,  s0i + s1i + s2i + s3i);
            V[(a0 +  8)*16 + n] = make_float2(s0r - s1i - s2r + s3i,  s0i + s1r - s2i - s3r);
            V[(a0 + 16)*16 + n] = make_float2(s0r - s1r + s2r - s3r,  s0i - s1i + s2i - s3i);
            V[(a0 + 24)*16 + n] = make_float2(s0r + s1i - s2r - s3i,  s0i - s1r - s2i + s3r);
        }
        __syncthreads();

        // stage 2 (radix-4 over n): one n-pass -> out[a][g], [g+8], [g+16], [g+24]
        // S_r = sum_{n≡r mod 4} V_n e^{2pi i n g/32}; out(g+8t) = c0 + 2*Re(sum_r i^{rt} S_r).
        // Even classes (r=0,2) only need real parts (i^{rt} = ±1 there).
        {
            int a2 = t2 >> 3, g = t2 & 7;              // a2 in 0..15, g in 0..7
            const float2* V = Vv + kp*512;
            size_t base = ((size_t)bo*32 + k)*1024;
            #pragma unroll
            for (int da = 0; da < 2; da++) {
                int a = a2*2 + da;
                float S0r=0.f, S1r=0.f, S1i=0.f, S2r=0.f, S3r=0.f, S3i=0.f;
                #pragma unroll
                for (int n = 1; n < 16; n++) {
                    float2 v = V[a*16 + n];            // broadcast
                    float2 e = cs16[(n+15)*16 + g];    // e^{+2pi i n g/32}
                    float tr = v.x*e.x - v.y*e.y;
                    const int r = n & 3;               // compile-time (unrolled)
                    if (r == 0)      { S0r += tr; }
                    else if (r == 2) { S2r += tr; }
                    else {
                        float ti = v.x*e.y + v.y*e.x;
                        if (r == 1) { S1r += tr; S1i += ti; }
                        else        { S3r += tr; S3i += ti; }
                    }
                }
                float c0 = bv + V[a*16].x;
                out[base + a*32 + g     ] = c0 + 2.f*(S0r + S1r + S2r + S3r);
                out[base + a*32 + g +  8] = c0 + 2.f*(S0r - S1i - S2r + S3i);
                out[base + a*32 + g + 16] = c0 + 2.f*(S0r - S1r + S2r - S3r);
                out[base + a*32 + g + 24] = c0 + 2.f*(S0r + S1i - S2r - S3i);
            }
        }
    }
}

extern "C" void kernel_launch(void* const* d_in, const int* in_sizes, int n_in,
                              void* d_out, int out_size) {
    const float* x       = (const float*)d_in[0];
    const float* kern    = (const float*)d_in[1];
    const float* bias    = (const float*)d_in[2];
    const float* wig_s2  = (const float*)d_in[3];
    const float* fk_re   = (const float*)d_in[4];
    const float* fk_im   = (const float*)d_in[5];
    const float* wig_so3 = (const float*)d_in[6];
    float* out = (float*)d_out;

    float scaling = 1.0f / sqrtf(32768.0f);

    cudaFuncSetAttribute(k_fz,   cudaFuncAttributeMaxDynamicSharedMemorySize, 65536);
    cudaFuncSetAttribute(k_main, cudaFuncAttributeMaxDynamicSharedMemorySize, 43200);

    k_fhat<<<dim3(16,16), 256>>>(x, wig_s2);
    k_prep<<<288, 256>>>(kern, fk_re, fk_im, scaling, wig_so3);
    k_fz  <<<1024, 512, 65536>>>();
    k_main<<<dim3(1024, 4), 256, 43200>>>(bias, out);
}

// round 12
// speedup vs baseline: 1.0268x; 1.0268x over previous
#include <cuda_runtime.h>
#include <math.h>

#define NSPEC  256
#define NSPEC3 5456
#define NPACK  2856   // sum over l of (2l+1)*(l+1)  — only nloc >= l kept

// scratch (static device globals — allowed)
__device__ float2 g_fhat [16*16*NSPEC];     // [b][f][s]
__device__ float2 g_psi  [16*64*NSPEC];     // [i][o][s]
__device__ float2 g_Fz   [1024*NPACK];      // [b*64+o][packed e]  (23.4 MB)
__device__ float  g_wig3p[32*NPACK];        // packed wig_so3
__device__ int    g_lut  [NPACK];           // packed (sm_ << 16) | sn for k_fz

__constant__ int c_offs[16] = {0,1,10,35,84,165,286,455,680,969,1330,1771,2300,2925,3654,4495};
__constant__ int c_offP[16] = {0,1,7,22,50,95,161,252,372,525,715,946,1222,1547,1925,2360};
// c_step[l] = (2l+3)(l+1): idx_{l+1} = idx_l + c_step[l] + m
__constant__ int c_step[15] = {3,10,21,36,55,78,105,136,171,210,253,300,351,406,465};

// ---------------- Kernel 1: fhat[b,f,s] (Hermitian fold over m + radix-2 fold over alpha) ----------------
__global__ void k_fhat(const float* __restrict__ x, const float* __restrict__ wig) {
    __shared__ float buf[8512];
    float*  sx   = buf;                       // [j*65 + a], a<64
    float2* xf   = (float2*)buf;              // [j*16 + m], m<16 (aliases sx after it is dead)
    float*  su   = buf + 4160;                // [j*33 + a], a<32: x[a]+x[a+32]
    float*  sv   = buf + 6272;                // [j*33 + a], a<32: x[a]-x[a+32]
    float2* cs64 = (float2*)(buf + 8384);     // e^{-2pi i t/64}
    int b = blockIdx.x, f = blockIdx.y, tid = threadIdx.x;
    if (tid < 64) { float sv_, cv; sincospif((float)tid/32.0f, &sv_, &cv); cs64[tid] = make_float2(cv, -sv_); }
    const float* xp = x + (size_t)(b*16+f)*4096;
    for (int p = tid; p < 4096; p += 256) sx[(p>>6)*65 + (p&63)] = xp[p];
    __syncthreads();
    for (int p = tid; p < 2048; p += 256) {           // u/v fold: 64 j x 32 a
        int j = p >> 5, a = p & 31;
        float lo = sx[j*65 + a], hi = sx[j*65 + a + 32];
        su[j*33 + a] = lo + hi;
        sv[j*33 + a] = lo - hi;
    }
    __syncthreads();
    for (int p = tid; p < 1024; p += 256) {           // 16 m-values (0..15) x 64 betas, 32 iters
        int m = p >> 6, j = p & 63;
        const float* row = (m & 1) ? &sv[j*33] : &su[j*33];
        float ar=0.f, ai=0.f;
        int t = 0;
        #pragma unroll 8
        for (int a = 0; a < 32; a++) {
            float2 e = cs64[t];                        // broadcast
            float v = row[a];
            ar += v*e.x;
            ai += v*e.y;
            t = (t + m) & 63;
        }
        xf[j*16+m] = make_float2(ar, ai);              // overwrites dead sx region
    }
    __syncthreads();
    int s = tid;
    int l = (int)sqrtf((float)s);
    while ((l+1)*(l+1) <= s) ++l;
    while (l*l > s) --l;
    int m = s - l*l - l;
    int am = m < 0 ? -m : m;
    float sgn = m < 0 ? -1.f : 1.f;                    // xf[-m] = conj(xf[m])
    float ar=0.f, ai=0.f;
    #pragma unroll 8
    for (int j = 0; j < 64; j++) {
        float w = wig[j*NSPEC + s];
        float2 v = xf[j*16+am];
        ar += w*v.x; ai += w*v.y;
    }
    g_fhat[(b*16+f)*NSPEC + s] = make_float2(ar, sgn*ai);
}

// ---------------- Kernel 2 (merged): blocks 0..255 = psi, blocks 256..287 = pack wig_so3 + LUT ----------------
__global__ void k_prep(const float* __restrict__ kern, const float* __restrict__ fkr,
                       const float* __restrict__ fki, float scaling,
                       const float* __restrict__ wig3) {
    int tid = threadIdx.x;
    if (blockIdx.x < 256) {
        __shared__ float2 fk[32];
        int s = blockIdx.x;
        if (tid < 32) fk[tid] = make_float2(fkr[s*32+tid]*scaling, fki[s*32+tid]*scaling);
        __syncthreads();
        for (int p = tid; p < 1024; p += 256) {        // p = i*64+o
            const float* kp = kern + p*32;
            float ar=0.f, ai=0.f;
            #pragma unroll
            for (int g = 0; g < 32; g++) { float kv = kp[g]; ar += kv*fk[g].x; ai += kv*fk[g].y; }
            g_psi[p*NSPEC + s] = make_float2(ar, ai);
        }
    } else {
        int k = blockIdx.x - 256;
        for (int p = tid; p < NPACK; p += 256) {
            int l = 15;
            while (c_offP[l] > p) --l;
            int r = p - c_offP[l];
            int mloc = r / (l+1);
            int nq   = r - mloc*(l+1);
            g_wig3p[k*NPACK + p] = wig3[k*NSPEC3 + c_offs[l] + mloc*(2*l+1) + (nq + l)];
            if (k == 0) {
                int sm_ = l*l + mloc;
                int sn  = l*l + nq + l;
                g_lut[p] = (sm_ << 16) | sn;
            }
        }
    }
}

// ---------------- Kernel 3: packed Fz (only n >= 0), split even/odd-i accumulators for ILP ----------------
__global__ void k_fz() {
    extern __shared__ float2 sm3[];
    float2* fh = sm3;          // [i*256+s]
    float2* ps = sm3 + 4096;   // [i*256+s]
    int bo = blockIdx.x, b = bo >> 6, o = bo & 63, tid = threadIdx.x;
    for (int p = tid; p < 4096; p += 512) {
        int i = p >> 8, s = p & 255;
        fh[p] = g_fhat[(b*16+i)*NSPEC + s];            // coalesced
        ps[p] = g_psi [(i*64+o)*NSPEC + s];            // coalesced
    }
    __syncthreads();
    for (int e = tid; e < NPACK; e += 512) {
        int lu = __ldg(&g_lut[e]);
        int sm_ = lu >> 16, sn = lu & 0xffff;
        float ar0=0.f, ai0=0.f, ar1=0.f, ai1=0.f;      // two chains, halved latency depth
        #pragma unroll
        for (int i = 0; i < 16; i += 2) {
            float2 a0 = fh[i*256 + sm_];
            float2 c0 = ps[i*256 + sn];
            float2 a1 = fh[(i+1)*256 + sm_];
            float2 c1 = ps[(i+1)*256 + sn];
            ar0 += a0.x*c0.x + a0.y*c0.y;              // fhat * conj(psi)
            ai0 += a0.y*c0.x - a0.x*c0.y;
            ar1 += a1.x*c1.x + a1.y*c1.y;
            ai1 += a1.y*c1.x - a1.x*c1.y;
        }
        g_Fz[(size_t)bo*NPACK + e] = make_float2(ar0 + ar1, ai0 + ai1);
    }
}

// ---------------- Kernel 4 (fused, Hermitian + radix-4 both axes, dual-k) ----------------
// grid (1024 bo, 4 kq); each block handles 8 beta_out values, 2 at a time.
// smem float2 units: Fz 2856 | spc 1024 (2x512) | Vv 1024 (2x512) | cs16 496
// total = (2856+1024+1024+496)*8 = 43200 B; __launch_bounds__(256,5) keeps 5 CTAs/SM
__global__ void __launch_bounds__(256, 5)
k_main(const float* __restrict__ bias, float* __restrict__ out) {
    extern __shared__ float smraw[];
    float2* Fz   = (float2*)smraw;     // 2856
    float2* spc  = Fz  + 2856;         // 1024: [kp*512 + mi*16 + nq]
    float2* Vv   = spc + 1024;         // 1024: [kp*512 + a*16 + nq]
    float2* cs16 = Vv  + 1024;         // 496:  cs16[q*16+r] = e^{+2pi i (q-15) r/32}, r<16
    int tid = threadIdx.x;
    int bo = blockIdx.x, o = bo & 63;
    int kq = blockIdx.y;

    for (int p = tid; p < 496; p += 256) {
        int q = p >> 4, r = p & 15;
        int t = ((q-15)*r) & 31;
        float sv, cv; sincospif((float)t / 16.0f, &sv, &cv);
        cs16[p] = make_float2(cv, sv);
    }
    for (int p = tid; p < NPACK; p += 256) Fz[p] = g_Fz[(size_t)bo*NPACK + p];
    float bv = bias[o];

    int kp = tid >> 7, t2 = tid & 127;
    float2* spcP = spc + kp*512;                        // this thread's k-plane buffers
    float2* VvP  = Vv  + kp*512;
    const float* wkg = g_wig3p + (kq*8 + kp)*NPACK;     // advanced by 2*NPACK per iter
    float* outk = out + ((size_t)bo*32 + kq*8 + kp)*1024;  // advanced by 2048 per iter

    __syncthreads();                                    // Fz/cs16 ready

    for (int kk4 = 0; kk4 < 4; kk4++) {
        // spec[m,n] for n>=0 (half-block per k-plane), incremental packed index.
        // No barrier at loop top: spec writes only spc; stage2 of the previous
        // iteration reads only Vv/cs16, and stage1 finished before its barrier.
        for (int p = t2; p < 496; p += 128) {
            int mi = p >> 4, nq = p & 15;
            int m = mi - 15;
            int am = m < 0 ? -m : m;
            int lmin = am > nq ? am : nq;
            float ar = 0.f, ai = 0.f;
            int idx = c_offP[lmin] + (m+lmin)*(lmin+1) + nq;
            for (int l = lmin; l < 16; l++) {
                float d = __ldg(&wkg[idx]);
                float2 fz = Fz[idx];
                ar += fz.x*d;
                ai += fz.y*d;
                if (l < 15) idx += c_step[l] + m;
            }
            spcP[p] = make_float2(ar, ai);
        }
        __syncthreads();

        // stage 1 (radix-4 over m): 31 cmacs -> V[a0], V[a0+8], V[a0+16], V[a0+24]
        {
            int a0 = t2 >> 4, n = t2 & 15;             // a0 in 0..7
            float s0r=0,s0i=0,s1r=0,s1i=0,s2r=0,s2i=0,s3r=0,s3i=0;
            const float2* sp0 = spcP + n;
            const float2* e0  = cs16 + a0;
            #pragma unroll
            for (int mi = 0; mi < 31; mi++) {
                float2 sp = sp0[mi*16];
                float2 e  = e0[mi*16];                 // e^{+2pi i (mi-15) a0/32}
                float tr = sp.x*e.x - sp.y*e.y;
                float ti = sp.x*e.y + sp.y*e.x;
                int r = (mi + 1) & 3;                  // (mi-15) mod 4
                if      (r == 0) { s0r += tr; s0i += ti; }
                else if (r == 1) { s1r += tr; s1i += ti; }
                else if (r == 2) { s2r += tr; s2i += ti; }
                else             { s3r += tr; s3i += ti; }
            }
            float2* Vp = VvP + a0*16 + n;
            Vp[  0] = make_float2(s0r + s1r + s2r + s3r,  s0i + s1i + s2i + s3i);
            Vp[128] = make_float2(s0r - s1i - s2r + s3i,  s0i + s1r - s2i - s3r);
            Vp[256] = make_float2(s0r - s1r + s2r - s3r,  s0i - s1i + s2i - s3i);
            Vp[384] = make_float2(s0r + s1i - s2r - s3i,  s0i - s1r - s2i + s3r);
        }
        __syncthreads();

        // stage 2 (radix-4 over n): one n-pass -> out[a][g], [g+8], [g+16], [g+24]
        // S_r = sum_{n≡r mod 4} V_n e^{2pi i n g/32}; out(g+8t) = c0 + 2*Re(sum_r i^{rt} S_r).
        {
            int a2 = t2 >> 3, g = t2 & 7;              // a2 in 0..15, g in 0..7
            const float2* eg = cs16 + 15*16 + g;       // eg[n*16] = e^{+2pi i n g/32}
            #pragma unroll
            for (int da = 0; da < 2; da++) {
                int a = a2*2 + da;
                const float2* Vp = VvP + a*16;
                float S0r=0.f, S1r=0.f, S1i=0.f, S2r=0.f, S3r=0.f, S3i=0.f;
                #pragma unroll
                for (int n = 1; n < 16; n++) {
                    float2 v = Vp[n];                  // broadcast
                    float2 e = eg[n*16];
                    float tr = v.x*e.x - v.y*e.y;
                    const int r = n & 3;               // compile-time (unrolled)
                    if (r == 0)      { S0r += tr; }
                    else if (r == 2) { S2r += tr; }
                    else {
                        float ti = v.x*e.y + v.y*e.x;
                        if (r == 1) { S1r += tr; S1i += ti; }
                        else        { S3r += tr; S3i += ti; }
                    }
                }
                float c0 = bv + Vp[0].x;
                float* op = outk + a*32 + g;
                op[ 0] = c0 + 2.f*(S0r + S1r + S2r + S3r);
                op[ 8] = c0 + 2.f*(S0r - S1i - S2r + S3i);
                op[16] = c0 + 2.f*(S0r - S1r + S2r - S3r);
                op[24] = c0 + 2.f*(S0r + S1i - S2r - S3i);
            }
        }
        wkg  += 2*NPACK;
        outk += 2048;
    }
}

extern "C" void kernel_launch(void* const* d_in, const int* in_sizes, int n_in,
                              void* d_out, int out_size) {
    const float* x       = (const float*)d_in[0];
    const float* kern    = (const float*)d_in[1];
    const float* bias    = (const float*)d_in[2];
    const float* wig_s2  = (const float*)d_in[3];
    const float* fk_re   = (const float*)d_in[4];
    const float* fk_im   = (const float*)d_in[5];
    const float* wig_so3 = (const float*)d_in[6];
    float* out = (float*)d_out;

    float scaling = 1.0f / sqrtf(32768.0f);

    cudaFuncSetAttribute(k_fz,   cudaFuncAttributeMaxDynamicSharedMemorySize, 65536);
    cudaFuncSetAttribute(k_main, cudaFuncAttributeMaxDynamicSharedMemorySize, 43200);

    k_fhat<<<dim3(16,16), 256>>>(x, wig_s2);
    k_prep<<<288, 256>>>(kern, fk_re, fk_im, scaling, wig_so3);
    k_fz  <<<1024, 512, 65536>>>();
    k_main<<<dim3(1024, 4), 256, 43200>>>(bias, out);
}

// round 13
// speedup vs baseline: 1.0747x; 1.0467x over previous
#include <cuda_runtime.h>
#include <math.h>

#define NSPEC  256
#define NSPEC3 5456
#define NPACK  2856   // sum over l of (2l+1)*(l+1)  — only nloc >= l kept

// scratch (static device globals — allowed)
__device__ float2 g_fhat [16*16*NSPEC];     // [b][f][s]
__device__ float2 g_psi  [16*64*NSPEC];     // [i][o][s]
__device__ float2 g_Fz   [1024*NPACK];      // [b*64+o][packed e]  (23.4 MB)
__device__ float  g_wig3p[32*NPACK];        // packed wig_so3
__device__ int    g_lut  [NPACK];           // packed (sm_ << 16) | sn for k_fz

__constant__ int c_offs[16] = {0,1,10,35,84,165,286,455,680,969,1330,1771,2300,2925,3654,4495};
__constant__ int c_offP[16] = {0,1,7,22,50,95,161,252,372,525,715,946,1222,1547,1925,2360};
// c_step[l] = (2l+3)(l+1): idx_{l+1} = idx_l + c_step[l] + m
__constant__ int c_step[15] = {3,10,21,36,55,78,105,136,171,210,253,300,351,406,465};

// ---------------- Kernel 1: fhat[b,f,s] (Hermitian fold over m + radix-2 fold over alpha) ----------------
__global__ void k_fhat(const float* __restrict__ x, const float* __restrict__ wig) {
    __shared__ float buf[8512];
    float*  sx   = buf;                       // [j*65 + a], a<64
    float2* xf   = (float2*)buf;              // [j*16 + m], m<16 (aliases sx after it is dead)
    float*  su   = buf + 4160;                // [j*33 + a], a<32: x[a]+x[a+32]
    float*  sv   = buf + 6272;                // [j*33 + a], a<32: x[a]-x[a+32]
    float2* cs64 = (float2*)(buf + 8384);     // e^{-2pi i t/64}
    int b = blockIdx.x, f = blockIdx.y, tid = threadIdx.x;
    if (tid < 64) { float sv_, cv; sincospif((float)tid/32.0f, &sv_, &cv); cs64[tid] = make_float2(cv, -sv_); }
    const float* xp = x + (size_t)(b*16+f)*4096;
    for (int p = tid; p < 4096; p += 256) sx[(p>>6)*65 + (p&63)] = xp[p];
    __syncthreads();
    for (int p = tid; p < 2048; p += 256) {           // u/v fold: 64 j x 32 a
        int j = p >> 5, a = p & 31;
        float lo = sx[j*65 + a], hi = sx[j*65 + a + 32];
        su[j*33 + a] = lo + hi;
        sv[j*33 + a] = lo - hi;
    }
    __syncthreads();
    for (int p = tid; p < 1024; p += 256) {           // 16 m-values (0..15) x 64 betas, 32 iters
        int m = p >> 6, j = p & 63;
        const float* row = (m & 1) ? &sv[j*33] : &su[j*33];
        float ar=0.f, ai=0.f;
        int t = 0;
        #pragma unroll 8
        for (int a = 0; a < 32; a++) {
            float2 e = cs64[t];                        // broadcast
            float v = row[a];
            ar += v*e.x;
            ai += v*e.y;
            t = (t + m) & 63;
        }
        xf[j*16+m] = make_float2(ar, ai);              // overwrites dead sx region
    }
    __syncthreads();
    int s = tid;
    int l = (int)sqrtf((float)s);
    while ((l+1)*(l+1) <= s) ++l;
    while (l*l > s) --l;
    int m = s - l*l - l;
    int am = m < 0 ? -m : m;
    float sgn = m < 0 ? -1.f : 1.f;                    // xf[-m] = conj(xf[m])
    float ar=0.f, ai=0.f;
    #pragma unroll 8
    for (int j = 0; j < 64; j++) {
        float w = wig[j*NSPEC + s];
        float2 v = xf[j*16+am];
        ar += w*v.x; ai += w*v.y;
    }
    g_fhat[(b*16+f)*NSPEC + s] = make_float2(ar, sgn*ai);
}

// ---------------- Kernel 2 (merged): blocks 0..255 = psi, blocks 256..287 = pack wig_so3 + LUT ----------------
__global__ void k_prep(const float* __restrict__ kern, const float* __restrict__ fkr,
                       const float* __restrict__ fki, float scaling,
                       const float* __restrict__ wig3) {
    int tid = threadIdx.x;
    if (blockIdx.x < 256) {
        __shared__ float2 fk[32];
        int s = blockIdx.x;
        if (tid < 32) fk[tid] = make_float2(fkr[s*32+tid]*scaling, fki[s*32+tid]*scaling);
        __syncthreads();
        for (int p = tid; p < 1024; p += 256) {        // p = i*64+o
            const float* kp = kern + p*32;
            float ar=0.f, ai=0.f;
            #pragma unroll
            for (int g = 0; g < 32; g++) { float kv = kp[g]; ar += kv*fk[g].x; ai += kv*fk[g].y; }
            g_psi[p*NSPEC + s] = make_float2(ar, ai);
        }
    } else {
        int k = blockIdx.x - 256;
        for (int p = tid; p < NPACK; p += 256) {
            int l = 15;
            while (c_offP[l] > p) --l;
            int r = p - c_offP[l];
            int mloc = r / (l+1);
            int nq   = r - mloc*(l+1);
            g_wig3p[k*NPACK + p] = wig3[k*NSPEC3 + c_offs[l] + mloc*(2*l+1) + (nq + l)];
            if (k == 0) {
                int sm_ = l*l + mloc;
                int sn  = l*l + nq + l;
                g_lut[p] = (sm_ << 16) | sn;
            }
        }
    }
}

// ---------------- Kernel 3: packed Fz (only n >= 0), split even/odd-i accumulators for ILP ----------------
__global__ void k_fz() {
    extern __shared__ float2 sm3[];
    float2* fh = sm3;          // [i*256+s]
    float2* ps = sm3 + 4096;   // [i*256+s]
    int bo = blockIdx.x, b = bo >> 6, o = bo & 63, tid = threadIdx.x;
    for (int p = tid; p < 4096; p += 512) {
        int i = p >> 8, s = p & 255;
        fh[p] = g_fhat[(b*16+i)*NSPEC + s];            // coalesced
        ps[p] = g_psi [(i*64+o)*NSPEC + s];            // coalesced
    }
    __syncthreads();
    for (int e = tid; e < NPACK; e += 512) {
        int lu = __ldg(&g_lut[e]);
        int sm_ = lu >> 16, sn = lu & 0xffff;
        float ar0=0.f, ai0=0.f, ar1=0.f, ai1=0.f;      // two chains, halved latency depth
        #pragma unroll
        for (int i = 0; i < 16; i += 2) {
            float2 a0 = fh[i*256 + sm_];
            float2 c0 = ps[i*256 + sn];
            float2 a1 = fh[(i+1)*256 + sm_];
            float2 c1 = ps[(i+1)*256 + sn];
            ar0 += a0.x*c0.x + a0.y*c0.y;              // fhat * conj(psi)
            ai0 += a0.y*c0.x - a0.x*c0.y;
            ar1 += a1.x*c1.x + a1.y*c1.y;
            ai1 += a1.y*c1.x - a1.x*c1.y;
        }
        g_Fz[(size_t)bo*NPACK + e] = make_float2(ar0 + ar1, ai0 + ai1);
    }
}

// ---------------- Kernel 4 (fused, Hermitian + radix-4 stage1, dual-k): R10 structure + [n][a] V layout ----------------
// grid (1024 bo, 4 kq); each block handles 8 beta_out values, 2 at a time.
// smem float2 units: Fz 2856 | spc 1024 (2x512, [kp*512+mi*16+nq]) | Vv 1088 (2x544, [kp*544+n*34+a])
//                    | cs16 496. total = 5464*8 = 43712 B -> 5 CTAs/SM
__global__ void __launch_bounds__(256, 5)
k_main(const float* __restrict__ bias, float* __restrict__ out) {
    extern __shared__ float smraw[];
    float2* Fz   = (float2*)smraw;     // 2856
    float2* spc  = Fz  + 2856;         // 1024: [kp*512 + mi*16 + nq]
    float2* Vv   = spc + 1024;         // 1088: [kp*544 + n*34 + a]  (34 stride keeps float4 16B-aligned)
    float2* cs16 = Vv  + 1088;         // 496:  cs16[q*16+r] = e^{+2pi i (q-15) r/32}, r<16
    int tid = threadIdx.x;
    int bo = blockIdx.x, o = bo & 63;
    int kq = blockIdx.y;

    for (int p = tid; p < 496; p += 256) {
        int q = p >> 4, r = p & 15;
        int t = ((q-15)*r) & 31;
        float sv, cv; sincospif((float)t / 16.0f, &sv, &cv);
        cs16[p] = make_float2(cv, sv);
    }
    for (int p = tid; p < NPACK; p += 256) Fz[p] = g_Fz[(size_t)bo*NPACK + p];
    float bv = bias[o];

    int kp = tid >> 7, t2 = tid & 127;

    for (int kk4 = 0; kk4 < 4; kk4++) {
        int k = kq*8 + kk4*2 + kp;
        __syncthreads();                               // prior stage2 done before spc/Vv rewrite

        // spec[m,n] for n>=0 (half-block per k-plane), incremental packed index (exact R10)
        const float* wkg = g_wig3p + k*NPACK;
        for (int p = t2; p < 496; p += 128) {
            int mi = p >> 4, nq = p & 15;
            int m = mi - 15;
            int am = m < 0 ? -m : m;
            int lmin = am > nq ? am : nq;
            float ar = 0.f, ai = 0.f;
            int idx = c_offP[lmin] + (m+lmin)*(lmin+1) + nq;
            for (int l = lmin; l < 16; l++) {
                float d = __ldg(&wkg[idx]);
                float2 fz = Fz[idx];
                ar += fz.x*d;
                ai += fz.y*d;
                if (l < 15) idx += c_step[l] + m;
            }
            spc[kp*512 + p] = make_float2(ar, ai);
        }
        __syncthreads();

        // stage 1 (radix-4 over m, exact R10 math): 31 cmacs -> V[n][a0], [a0+8], [a0+16], [a0+24]
        {
            int a0 = t2 >> 4, n = t2 & 15;             // a0 in 0..7
            float s0r=0,s0i=0,s1r=0,s1i=0,s2r=0,s2i=0,s3r=0,s3i=0;
            #pragma unroll
            for (int mi = 0; mi < 31; mi++) {
                float2 sp = spc[kp*512 + mi*16 + n];
                float2 e  = cs16[mi*16 + a0];          // e^{+2pi i (mi-15) a0/32}
                float tr = sp.x*e.x - sp.y*e.y;
                float ti = sp.x*e.y + sp.y*e.x;
                int r = (mi + 1) & 3;                  // (mi-15) mod 4
                if      (r == 0) { s0r += tr; s0i += ti; }
                else if (r == 1) { s1r += tr; s1i += ti; }
                else if (r == 2) { s2r += tr; s2i += ti; }
                else             { s3r += tr; s3i += ti; }
            }
            float2* V = Vv + kp*544 + n*34 + a0;       // [n][a] layout
            V[ 0] = make_float2(s0r + s1r + s2r + s3r,  s0i + s1i + s2i + s3i);
            V[ 8] = make_float2(s0r - s1i - s2r + s3i,  s0i + s1r - s2i - s3r);
            V[16] = make_float2(s0r - s1r + s2r - s3r,  s0i - s1i + s2i - s3i);
            V[24] = make_float2(s0r + s1i - s2r - s3i,  s0i - s1r - s2i + s3r);
        }
        __syncthreads();

        // stage 2 (radix-2 over n, R10's 8-chain structure; v loads as 2x LDS.128 per n)
        {
            int hi = t2 >> 4, lo = t2 & 15;            // hi in 0..7, g = lo
            const float2* V = Vv + kp*544;
            int a0 = hi*4;
            float4 w01 = *(const float4*)(V + a0);     // n=0: V[0][a0], V[0][a0+1]
            float4 w23 = *(const float4*)(V + a0 + 2);
            float c0 = bv + w01.x;
            float c1 = bv + w01.z;
            float c2 = bv + w23.x;
            float c3 = bv + w23.z;
            float se0=0,so0=0,se1=0,so1=0,se2=0,so2=0,se3=0,so3=0;
            #pragma unroll
            for (int n = 1; n < 16; n++) {
                float2 e = cs16[(n+15)*16 + lo];       // e^{+2pi i n g/32}
                float4 v01 = *(const float4*)(V + n*34 + a0);      // broadcast LDS.128
                float4 v23 = *(const float4*)(V + n*34 + a0 + 2);
                float t0 = v01.x*e.x - v01.y*e.y;
                float t1 = v01.z*e.x - v01.w*e.y;
                float t2r = v23.x*e.x - v23.y*e.y;
                float t3 = v23.z*e.x - v23.w*e.y;
                if (n & 1) { so0 += t0; so1 += t1; so2 += t2r; so3 += t3; }
                else       { se0 += t0; se1 += t1; se2 += t2r; se3 += t3; }
            }
            size_t base = ((size_t)bo*32 + k)*1024;
            out[base + (a0+0)*32 + lo     ] = c0 + 2.f*(se0 + so0);
            out[base + (a0+0)*32 + lo + 16] = c0 + 2.f*(se0 - so0);
            out[base + (a0+1)*32 + lo     ] = c1 + 2.f*(se1 + so1);
            out[base + (a0+1)*32 + lo + 16] = c1 + 2.f*(se1 - so1);
            out[base + (a0+2)*32 + lo     ] = c2 + 2.f*(se2 + so2);
            out[base + (a0+2)*32 + lo + 16] = c2 + 2.f*(se2 - so2);
            out[base + (a0+3)*32 + lo     ] = c3 + 2.f*(se3 + so3);
            out[base + (a0+3)*32 + lo + 16] = c3 + 2.f*(se3 - so3);
        }
    }
}

extern "C" void kernel_launch(void* const* d_in, const int* in_sizes, int n_in,
                              void* d_out, int out_size) {
    const float* x       = (const float*)d_in[0];
    const float* kern    = (const float*)d_in[1];
    const float* bias    = (const float*)d_in[2];
    const float* wig_s2  = (const float*)d_in[3];
    const float* fk_re   = (const float*)d_in[4];
    const float* fk_im   = (const float*)d_in[5];
    const float* wig_so3 = (const float*)d_in[6];
    float* out = (float*)d_out;

    float scaling = 1.0f / sqrtf(32768.0f);

    cudaFuncSetAttribute(k_fz,   cudaFuncAttributeMaxDynamicSharedMemorySize, 65536);
    cudaFuncSetAttribute(k_main, cudaFuncAttributeMaxDynamicSharedMemorySize, 43712);

    k_fhat<<<dim3(16,16), 256>>>(x, wig_s2);
    k_prep<<<288, 256>>>(kern, fk_re, fk_im, scaling, wig_so3);
    k_fz  <<<1024, 512, 65536>>>();
    k_main<<<dim3(1024, 4), 256, 43712>>>(bias, out);
}